// round 16
// baseline (speedup 1.0000x reference)
#include <cuda_runtime.h>
#include <cuda_fp16.h>

#define B_  128
#define L_  512
#define DK_ 64
#define SSH 260         // S(half) row stride in u32 (520 halves)
#define PS  36          // bias panel row stride (floats)
#define STH 36          // staging row stride in u32 (72 halves); 144B rows
#define SLOT_U32   (32*STH)           // 1152 u32 = 4608 B per staging slot
#define SH_U32     (32*SSH)           // 8320
#define PAN_U32    (3*32*PS)          // 3456
#define STG_U32    (6*SLOT_U32)       // 6912: k-ring 3 + p-ring 3 (PV uses all 6 as V ring)
#define PAN_OFF    SH_U32
#define STG_OFF    (SH_U32 + PAN_U32)                 // 11776
#define SMEM_U32   (SH_U32 + PAN_U32 + STG_U32)       // 18688 u32 = 74752 B -> 3 CTAs/SM

// fp16 operand scratch (pre-converted once per launch)
__device__ __half g_kh[B_ * L_ * DK_];
__device__ __half g_vh[B_ * L_ * DK_];
__device__ __half g_ph[B_ * 2 * L_ * DK_];

// mask dtype mode: 0 = int32, 1 = uint8 (1-byte bool), 2 = float32
__device__ int g_mask_mode;

// half2 from two floats: low = lo, high = hi
__device__ __forceinline__ unsigned h2pack(float hi, float lo){
    unsigned r; asm("cvt.rn.f16x2.f32 %0, %1, %2;" : "=r"(r) : "f"(hi), "f"(lo)); return r;
}

// f32 -> f16 conversion for k, v, pos; block 0 also probes mask dtype.
__global__ void cvt_kernel(const float* __restrict__ k, const float* __restrict__ v,
                           const float* __restrict__ pos, const unsigned* __restrict__ m){
    if (blockIdx.x == 0){
        __shared__ int mode;
        if (threadIdx.x == 0) mode = 0;
        __syncthreads();
        int local = 0;
        for (int i = threadIdx.x; i < 8192; i += blockDim.x){
            unsigned vv = m[i];
            if (vv == 0x3F800000u) local |= 2;
            else if (vv > 1u)      local |= 1;
        }
        if (local) atomicOr(&mode, local);
        __syncthreads();
        if (threadIdx.x == 0) g_mask_mode = (mode & 2) ? 2 : (mode & 1);
    }
    const int NK = B_ * L_ * DK_ / 4;
    const int NP = B_ * 2 * L_ * DK_ / 4;
    const int stride = gridDim.x * blockDim.x;
    for (int i = blockIdx.x * blockDim.x + threadIdx.x; i < NK; i += stride){
        float4 a = reinterpret_cast<const float4*>(k)[i];
        uint2 h; h.x = h2pack(a.y, a.x); h.y = h2pack(a.w, a.z);
        reinterpret_cast<uint2*>(g_kh)[i] = h;
        float4 b = reinterpret_cast<const float4*>(v)[i];
        uint2 hv; hv.x = h2pack(b.y, b.x); hv.y = h2pack(b.w, b.z);
        reinterpret_cast<uint2*>(g_vh)[i] = hv;
    }
    for (int i = blockIdx.x * blockDim.x + threadIdx.x; i < NP; i += stride){
        float4 a = reinterpret_cast<const float4*>(pos)[i];
        uint2 h; h.x = h2pack(a.y, a.x); h.y = h2pack(a.w, a.z);
        reinterpret_cast<uint2*>(g_ph)[i] = h;
    }
}

// FMA-pipe exp(y) * 2^-4 (scale folded into exponent splice; cancels in softmax).
__device__ __forceinline__ float fexp4(float y){
    float t = y * 1.44269504088896f;
    float z = t + 12582912.0f;
    int   n = __float_as_int(z) - 0x4B400000 - 4;
    float f = t - (z - 12582912.0f);
    float p =             1.3333558e-3f;
    p = fmaf(p, f, 9.6181291e-3f);
    p = fmaf(p, f, 5.5504109e-2f);
    p = fmaf(p, f, 2.4022651e-1f);
    p = fmaf(p, f, 6.9314718e-1f);
    p = fmaf(p, f, 1.0f);
    return __int_as_float(__float_as_int(p) + (n << 23));
}

__device__ __forceinline__ void hmma16(float d[4], unsigned a0, unsigned a1, unsigned a2,
                                       unsigned a3, unsigned b0, unsigned b1){
    asm volatile(
        "mma.sync.aligned.m16n8k16.row.col.f32.f16.f16.f32 "
        "{%0,%1,%2,%3}, {%4,%5,%6,%7}, {%8,%9}, {%0,%1,%2,%3};\n"
        : "+f"(d[0]), "+f"(d[1]), "+f"(d[2]), "+f"(d[3])
        : "r"(a0), "r"(a1), "r"(a2), "r"(a3), "r"(b0), "r"(b1));
}

__device__ __forceinline__ void ldsm_x4(unsigned r[4], unsigned addr){
    asm volatile("ldmatrix.sync.aligned.m8n8.x4.shared.b16 {%0,%1,%2,%3}, [%4];"
        : "=r"(r[0]), "=r"(r[1]), "=r"(r[2]), "=r"(r[3]) : "r"(addr));
}
__device__ __forceinline__ void ldsm_x4t(unsigned r[4], unsigned addr){
    asm volatile("ldmatrix.sync.aligned.m8n8.x4.trans.shared.b16 {%0,%1,%2,%3}, [%4];"
        : "=r"(r[0]), "=r"(r[1]), "=r"(r[2]), "=r"(r[3]) : "r"(addr));
}

// cp.async one 32x64-half chunk (4KB contiguous gmem) into a staging slot.
__device__ __forceinline__ void stage_cp(unsigned dstbase, const __half* __restrict__ src, int tid){
    unsigned dst = dstbase + (unsigned)(((tid >> 3) * STH + (tid & 7) * 4) * 4);
    asm volatile("cp.async.cg.shared.global [%0], [%1], 16;" :: "r"(dst), "l"(src + tid * 8));
}
#define CP_COMMIT() asm volatile("cp.async.commit_group;")
#define CP_WAIT(n)  asm volatile("cp.async.wait_group %0;" :: "n"(n))

// 32x32 score tile (K=64 fp16): B via 2x ldmatrix.x4 from staged slot.
__device__ __forceinline__ void mma_tile_h(const unsigned (&a)[4][4], unsigned addr, float o[4]){
    unsigned r[8];
    ldsm_x4(r,     addr);
    ldsm_x4(r + 4, addr + 64);
    o[0] = o[1] = o[2] = o[3] = 0.f;
    hmma16(o, a[0][0], a[0][1], a[0][2], a[0][3], r[0], r[1]);
    hmma16(o, a[1][0], a[1][1], a[1][2], a[1][3], r[2], r[3]);
    hmma16(o, a[2][0], a[2][1], a[2][2], a[2][3], r[4], r[5]);
    hmma16(o, a[3][0], a[3][1], a[3][2], a[3][3], r[6], r[7]);
}

__device__ __forceinline__ void ld_mask2(const char* __restrict__ mbase, size_t off, int mmode,
                                         int& m0, int& m1){
    if (mmode == 0){
        const int2 t = __ldcs(reinterpret_cast<const int2*>(mbase + 4 * off));
        m0 = (t.x != 0); m1 = (t.y != 0);
    } else if (mmode == 1){
        const unsigned char* p = reinterpret_cast<const unsigned char*>(mbase) + off;
        m0 = (p[0] != 0); m1 = (p[1] != 0);
    } else {
        const float2 t = __ldcs(reinterpret_cast<const float2*>(mbase + 4 * off));
        m0 = (t.x != 0.f); m1 = (t.y != 0.f);
    }
}

// Pack one row's 32 mask values (16 stages x 2 cols at cbl) into a u32 bitmask.
// 16 independent LDGs -> full MLP; hidden behind prologue.
__device__ __forceinline__ unsigned pack_mask_row(const char* __restrict__ mbase, size_t rowoff,
                                                  int cbl, int mmode){
    unsigned bits = 0;
    #pragma unroll
    for (int st = 0; st < 16; ++st){
        int m0, m1;
        ld_mask2(mbase, rowoff + st * 32 + cbl, mmode, m0, m1);
        bits |= ((unsigned)m0 << (2 * st)) | ((unsigned)m1 << (2 * st + 1));
    }
    return bits;
}

extern __shared__ float smem[];

__global__ void __launch_bounds__(256, 3)
sdpa_kernel(const float* __restrict__ q, const char* __restrict__ mask,
            float* __restrict__ out, float* __restrict__ attn)
{
    unsigned* ShU = reinterpret_cast<unsigned*>(smem);          // S as half2 words
    float*    pan = smem + PAN_OFF;
    const unsigned sbase = (unsigned)__cvta_generic_to_shared(smem);
    const unsigned stg_b = sbase + STG_OFF * 4;
    #define KSLOT(s) (stg_b + (unsigned)(s) * (SLOT_U32 * 4))          // slots 0..2
    #define PSLOT(s) (stg_b + (unsigned)(3 + (s)) * (SLOT_U32 * 4))    // slots 3..5
    #define VSLOT(s) (stg_b + (unsigned)(s) * (SLOT_U32 * 4))          // 6-slot V ring

    const int tid  = threadIdx.x;
    const int w    = tid >> 5, lane = tid & 31;
    const int mw   = w & 1,    nw   = w >> 1;
    const int gr   = lane >> 2, c4  = lane & 3;
    const int b    = blockIdx.x >> 4;
    const int q0   = (blockIdx.x & 15) * 32;
    const int mmode = g_mask_mode;

    const __half* kh = g_kh + (size_t)b * L_ * DK_;
    const __half* vh = g_vh + (size_t)b * L_ * DK_;
    const __half* ph = g_ph + ((size_t)b * (2 * L_) + q0) * DK_;

    // ---- prologue prefetch: {k0,p0,p1}, {k1,p2} ----
    stage_cp(KSLOT(0), kh,            tid);
    stage_cp(PSLOT(0), ph,            tid);
    stage_cp(PSLOT(1), ph + 32 * DK_, tid);
    CP_COMMIT();
    stage_cp(KSLOT(1), kh + 32 * DK_, tid);
    stage_cp(PSLOT(2), ph + 64 * DK_, tid);
    CP_COMMIT();

    // ---- lane offsets for ldmatrix (bytes) ----
    const int li  = lane & 7, lg = lane >> 3;
    const unsigned qk_off  = (unsigned)((nw*8 + li) * (STH*4) + lg * 16);
    const unsigned pvA_off = (unsigned)((mw*16 + (lg&1)*8 + li) * (SSH*4) + (lg>>1) * 16);
    const unsigned pvB_off = (unsigned)(((lg&1)*8 + li) * (STH*4) + (nw*8 + (lg>>1)*4) * 4);

    const int r0  = mw * 16 + gr;
    const int cbl = nw * 8 + 2 * c4;

    // ---- pack mask bits for both rows (64 LDGs, huge MLP, overlaps prologue) ----
    const size_t mrow0 = ((size_t)b * L_ + q0 + r0) * L_;
    const size_t mrow1 = mrow0 + (size_t)8 * L_;
    const unsigned mb0 = pack_mask_row(mask, mrow0, cbl, mmode);
    const unsigned mb1 = pack_mask_row(mask, mrow1, cbl, mmode);

    // ---- Q A-fragments (fp16), persist entire kernel ----
    unsigned aqh[4][4];
    {
        const float* qb = q + ((size_t)b * L_ + q0 + mw * 16) * DK_;
        #pragma unroll
        for (int ks = 0; ks < 4; ++ks){
            const int dk0 = ks * 16 + 2 * c4;
            float2 t00 = *reinterpret_cast<const float2*>(qb + gr       * DK_ + dk0);
            float2 t10 = *reinterpret_cast<const float2*>(qb + (gr + 8) * DK_ + dk0);
            float2 t01 = *reinterpret_cast<const float2*>(qb + gr       * DK_ + dk0 + 8);
            float2 t11 = *reinterpret_cast<const float2*>(qb + (gr + 8) * DK_ + dk0 + 8);
            aqh[ks][0] = h2pack(t00.y, t00.x);
            aqh[ks][1] = h2pack(t10.y, t10.x);
            aqh[ks][2] = h2pack(t01.y, t01.x);
            aqh[ks][3] = h2pack(t11.y, t11.x);
        }
    }

    CP_WAIT(1);          // {k0,p0,p1} landed
    __syncthreads();

    // ---- bias panel 0 -> slot 0 ----
    {
        float c[4]; mma_tile_h(aqh, PSLOT(0) + qk_off, c);
        float* pd = pan;
        *reinterpret_cast<float2*>(pd + r0*PS + cbl)     = make_float2(c[0], c[1]);
        *reinterpret_cast<float2*>(pd + (r0+8)*PS + cbl) = make_float2(c[2], c[3]);
    }
    __syncthreads();     // P-slot 0 reads complete before st=0 overwrites it (mod-3 ring)

    // ---- QK loop: cp.async 2-stage prefetch, 1 sync/stage, 3 rotating panels ----
    float psum0 = 0.f, psum1 = 0.f;

    #pragma unroll
    for (int st = 0; st < 16; ++st){
        const int slotA = st % 3;
        const int slotB = (st + 1) % 3;
        if (st < 14){
            stage_cp(KSLOT((st + 2) % 3), kh + (size_t)(st + 2) * 32 * DK_, tid);
            stage_cp(PSLOT(st % 3),       ph + (size_t)(st + 3) * 32 * DK_, tid);
        }
        CP_COMMIT();

        // bias panel st+1 from p-ring slot (st+1)%3 -> pan slot slotB
        {
            float c[4];
            mma_tile_h(aqh, PSLOT((st + 1) % 3) + qk_off, c);
            float* pd = pan + slotB * (32 * PS);
            *reinterpret_cast<float2*>(pd + r0*PS + cbl)     = make_float2(c[0], c[1]);
            *reinterpret_cast<float2*>(pd + (r0+8)*PS + cbl) = make_float2(c[2], c[3]);
        }
        // QK stage st
        float s[4];
        mma_tile_h(aqh, KSLOT(st % 3) + qk_off, s);

        CP_WAIT(1);       // chunk set for stage st+1 landed
        __syncthreads();  // panel slotB visible; staging ring coherent

        const float* pA = pan + slotA * (32 * PS);
        const float* pB = pan + slotB * (32 * PS);
        {
            const int m00 = (mb0 >> (2*st))     & 1;
            const int m01 = (mb0 >> (2*st + 1)) & 1;
            const int m10 = (mb1 >> (2*st))     & 1;
            const int m11 = (mb1 >> (2*st + 1)) & 1;
            int i0 = r0, i1 = r0 + 8;
            int idx;
            idx = i0 + cbl;     float c0 = (idx < 32 ? pA : pB)[i0*PS + (idx & 31)];
            idx = i0 + cbl + 1; float c1 = (idx < 32 ? pA : pB)[i0*PS + (idx & 31)];
            idx = i1 + cbl;     float c2 = (idx < 32 ? pA : pB)[i1*PS + (idx & 31)];
            idx = i1 + cbl + 1; float c3 = (idx < 32 ? pA : pB)[i1*PS + (idx & 31)];
            s[0] = m00 ? 0.f : fexp4((s[0] + c0) * 0.125f);
            s[1] = m01 ? 0.f : fexp4((s[1] + c1) * 0.125f);
            s[2] = m10 ? 0.f : fexp4((s[2] + c2) * 0.125f);
            s[3] = m11 ? 0.f : fexp4((s[3] + c3) * 0.125f);
        }
        psum0 += s[0] + s[1];
        psum1 += s[2] + s[3];
        const int scol = st * 16 + nw * 4 + c4;
        ShU[r0      * SSH + scol] = h2pack(s[1], s[0]);
        ShU[(r0+8)  * SSH + scol] = h2pack(s[3], s[2]);
    }
    __syncthreads();   // S(exp) writes + last panel reads complete

    // ---- V prefetch into 6-slot ring (hidden behind sum-reduce) ----
    stage_cp(VSLOT(0), vh,            tid);
    stage_cp(VSLOT(1), vh + 32 * DK_, tid);
    CP_COMMIT();
    stage_cp(VSLOT(2), vh + 64 * DK_, tid);
    stage_cp(VSLOT(3), vh + 96 * DK_, tid);
    CP_COMMIT();

    // ---- publish per-thread row sums ----
    float* sumbuf  = pan;          // 32*16 floats
    float* rinvbuf = pan + 1024;   // 32 floats
    sumbuf[r0 * 16 + nw * 4 + c4]       = psum0;
    sumbuf[(r0 + 8) * 16 + nw * 4 + c4] = psum1;
    __syncthreads();

    // ---- sum-reduce only: stash rinv (attn writes folded into PV loop) ----
    {
        const int row = tid >> 3, g = tid & 7;
        float sum = sumbuf[row * 16 + g] + sumbuf[row * 16 + g + 8];
        #pragma unroll
        for (int o = 4; o; o >>= 1) sum += __shfl_xor_sync(0xffffffffu, sum, o, 8);
        if (g == 0) rinvbuf[row] = 1.0f / sum;
    }
    CP_WAIT(1);        // v chunks 0,1 landed (2,3 may still be in flight)
    __syncthreads();   // rinvbuf + v0/v1 staging visible

    // ---- O = (P' @ V)_fp16 * rinv[row]; attn writes interleaved per super-stage ----
    {
        float o[2][4];
        #pragma unroll
        for (int tt = 0; tt < 2; ++tt)
            #pragma unroll
            for (int i = 0; i < 4; ++i) o[tt][i] = 0.f;

        const int row8 = tid >> 3, g8 = tid & 7;
        const unsigned* SrA = ShU + row8 * SSH;
        const float rinvA = rinvbuf[row8];
        float* ar = attn ? (attn + ((size_t)b * L_ + q0 + row8) * L_) : (float*)0;

        const unsigned aSa = sbase + pvA_off;
        #pragma unroll
        for (int s = 0; s < 8; ++s){
            if (s < 6){
                stage_cp(VSLOT((2*s + 4) % 6), vh + (size_t)(2*s + 4) * 32 * DK_, tid);
                stage_cp(VSLOT((2*s + 5) % 6), vh + (size_t)(2*s + 5) * 32 * DK_, tid);
            }
            CP_COMMIT();
            #pragma unroll
            for (int h = 0; h < 2; ++h){
                const int c = 2*s + h;
                unsigned aS[8];
                ldsm_x4(aS,     aSa + c * 64);
                ldsm_x4(aS + 4, aSa + c * 64 + 32);
                const unsigned vba = VSLOT(c % 6) + pvB_off;
                unsigned bV[8];
                ldsm_x4t(bV,     vba);
                ldsm_x4t(bV + 4, vba + 16 * STH * 4);
                hmma16(o[0], aS[0], aS[1], aS[2], aS[3], bV[0], bV[1]);
                hmma16(o[1], aS[0], aS[1], aS[2], aS[3], bV[2], bV[3]);
                hmma16(o[0], aS[4], aS[5], aS[6], aS[7], bV[4], bV[5]);
                hmma16(o[1], aS[4], aS[5], aS[6], aS[7], bV[6], bV[7]);
            }
            // attn chunks jj = 2s, 2s+1 (overlap STG with cp.async landing)
            if (ar){
                #pragma unroll
                for (int h = 0; h < 2; ++h){
                    const int jj = 2*s + h;
                    const int cw = jj * 16 + g8 * 2;
                    uint2 u = *reinterpret_cast<const uint2*>(SrA + cw);
                    float2 f01 = __half22float2(*reinterpret_cast<__half2*>(&u.x));
                    float2 f23 = __half22float2(*reinterpret_cast<__half2*>(&u.y));
                    float4 sv;
                    sv.x = f01.x * rinvA; sv.y = f01.y * rinvA;
                    sv.z = f23.x * rinvA; sv.w = f23.y * rinvA;
                    __stcs(reinterpret_cast<float4*>(ar + jj * 32 + g8 * 4), sv);
                }
            }
            CP_WAIT(1);
            __syncthreads();
        }
        const float rv0 = rinvbuf[r0];
        const float rv1 = rinvbuf[r0 + 8];
        #pragma unroll
        for (int tt = 0; tt < 2; ++tt){
            const int d0 = nw * 16 + tt * 8 + 2 * c4;
            size_t base0 = ((size_t)b * L_ + q0 + mw*16 + gr) * DK_ + d0;
            __stcs(reinterpret_cast<float2*>(out + base0),
                   make_float2(o[tt][0] * rv0, o[tt][1] * rv0));
            __stcs(reinterpret_cast<float2*>(out + base0 + (size_t)8 * DK_),
                   make_float2(o[tt][2] * rv1, o[tt][3] * rv1));
        }
    }
    #undef KSLOT
    #undef PSLOT
    #undef VSLOT
}

extern "C" void kernel_launch(void* const* d_in, const int* in_sizes, int n_in,
                              void* d_out, int out_size)
{
    const float* q   = (const float*)d_in[0];
    const float* k   = (const float*)d_in[1];
    const float* v   = (const float*)d_in[2];
    const float* pos = (const float*)d_in[3];
    const char*  mask = (const char*)d_in[4];
    float* out = (float*)d_out;

    const long long out_n = (long long)B_ * L_ * DK_;
    const long long att_n = (long long)B_ * L_ * L_;
    float* attn = ((long long)out_size >= out_n + att_n) ? (out + out_n) : nullptr;

    cvt_kernel<<<2048, 256>>>(k, v, pos, (const unsigned*)mask);

    const int smem_bytes = SMEM_U32 * 4;   // 74,752 B -> 3 CTAs/SM
    cudaFuncSetAttribute(sdpa_kernel, cudaFuncAttributeMaxDynamicSharedMemorySize, smem_bytes);
    sdpa_kernel<<<B_ * (L_ / 32), 256, smem_bytes>>>(q, mask, out, attn);
}

// round 17
// speedup vs baseline: 1.4798x; 1.4798x over previous
#include <cuda_runtime.h>
#include <cuda_fp16.h>

#define B_  128
#define L_  512
#define DK_ 64
#define SSH 260         // S(half) row stride in u32 (520 halves)
#define PS  36          // bias panel row stride (floats)
#define STH 36          // staging row stride in u32 (72 halves); 144B rows
#define SLOT_U32   (32*STH)           // 1152 u32 = 4608 B per staging slot
#define SH_U32     (32*SSH)           // 8320
#define PAN_U32    (3*32*PS)          // 3456
#define STG_U32    (6*SLOT_U32)       // 6912: k-ring 3 + p-ring 3 (PV uses all 6 as V ring)
#define PAN_OFF    SH_U32
#define STG_OFF    (SH_U32 + PAN_U32)                 // 11776
#define SMEM_U32   (SH_U32 + PAN_U32 + STG_U32)       // 18688 u32 = 74752 B -> 3 CTAs/SM

// fp16 operand scratch (pre-converted once per launch)
__device__ __half g_kh[B_ * L_ * DK_];
__device__ __half g_vh[B_ * L_ * DK_];
__device__ __half g_ph[B_ * 2 * L_ * DK_];

// mask dtype mode: 0 = int32, 1 = uint8 (1-byte bool), 2 = float32
__device__ int g_mask_mode;

// half2 from two floats: low = lo, high = hi
__device__ __forceinline__ unsigned h2pack(float hi, float lo){
    unsigned r; asm("cvt.rn.f16x2.f32 %0, %1, %2;" : "=r"(r) : "f"(hi), "f"(lo)); return r;
}

// f32 -> f16 conversion for k, v, pos; block 0 also probes mask dtype.
__global__ void cvt_kernel(const float* __restrict__ k, const float* __restrict__ v,
                           const float* __restrict__ pos, const unsigned* __restrict__ m){
    if (blockIdx.x == 0){
        __shared__ int mode;
        if (threadIdx.x == 0) mode = 0;
        __syncthreads();
        int local = 0;
        for (int i = threadIdx.x; i < 8192; i += blockDim.x){
            unsigned vv = m[i];
            if (vv == 0x3F800000u) local |= 2;
            else if (vv > 1u)      local |= 1;
        }
        if (local) atomicOr(&mode, local);
        __syncthreads();
        if (threadIdx.x == 0) g_mask_mode = (mode & 2) ? 2 : (mode & 1);
    }
    const int NK = B_ * L_ * DK_ / 4;
    const int NP = B_ * 2 * L_ * DK_ / 4;
    const int stride = gridDim.x * blockDim.x;
    for (int i = blockIdx.x * blockDim.x + threadIdx.x; i < NK; i += stride){
        float4 a = reinterpret_cast<const float4*>(k)[i];
        uint2 h; h.x = h2pack(a.y, a.x); h.y = h2pack(a.w, a.z);
        reinterpret_cast<uint2*>(g_kh)[i] = h;
        float4 b = reinterpret_cast<const float4*>(v)[i];
        uint2 hv; hv.x = h2pack(b.y, b.x); hv.y = h2pack(b.w, b.z);
        reinterpret_cast<uint2*>(g_vh)[i] = hv;
    }
    for (int i = blockIdx.x * blockDim.x + threadIdx.x; i < NP; i += stride){
        float4 a = reinterpret_cast<const float4*>(pos)[i];
        uint2 h; h.x = h2pack(a.y, a.x); h.y = h2pack(a.w, a.z);
        reinterpret_cast<uint2*>(g_ph)[i] = h;
    }
}

// FMA-pipe exp(y) * 2^-4 (scale folded into exponent splice; cancels in softmax).
__device__ __forceinline__ float fexp4(float y){
    float t = y * 1.44269504088896f;
    float z = t + 12582912.0f;
    int   n = __float_as_int(z) - 0x4B400000 - 4;
    float f = t - (z - 12582912.0f);
    float p =             1.3333558e-3f;
    p = fmaf(p, f, 9.6181291e-3f);
    p = fmaf(p, f, 5.5504109e-2f);
    p = fmaf(p, f, 2.4022651e-1f);
    p = fmaf(p, f, 6.9314718e-1f);
    p = fmaf(p, f, 1.0f);
    return __int_as_float(__float_as_int(p) + (n << 23));
}

__device__ __forceinline__ void hmma16(float d[4], unsigned a0, unsigned a1, unsigned a2,
                                       unsigned a3, unsigned b0, unsigned b1){
    asm volatile(
        "mma.sync.aligned.m16n8k16.row.col.f32.f16.f16.f32 "
        "{%0,%1,%2,%3}, {%4,%5,%6,%7}, {%8,%9}, {%0,%1,%2,%3};\n"
        : "+f"(d[0]), "+f"(d[1]), "+f"(d[2]), "+f"(d[3])
        : "r"(a0), "r"(a1), "r"(a2), "r"(a3), "r"(b0), "r"(b1));
}

__device__ __forceinline__ void ldsm_x4(unsigned r[4], unsigned addr){
    asm volatile("ldmatrix.sync.aligned.m8n8.x4.shared.b16 {%0,%1,%2,%3}, [%4];"
        : "=r"(r[0]), "=r"(r[1]), "=r"(r[2]), "=r"(r[3]) : "r"(addr));
}
__device__ __forceinline__ void ldsm_x4t(unsigned r[4], unsigned addr){
    asm volatile("ldmatrix.sync.aligned.m8n8.x4.trans.shared.b16 {%0,%1,%2,%3}, [%4];"
        : "=r"(r[0]), "=r"(r[1]), "=r"(r[2]), "=r"(r[3]) : "r"(addr));
}

// cp.async one 32x64-half chunk (4KB contiguous gmem) into a staging slot.
__device__ __forceinline__ void stage_cp(unsigned dstbase, const __half* __restrict__ src, int tid){
    unsigned dst = dstbase + (unsigned)(((tid >> 3) * STH + (tid & 7) * 4) * 4);
    asm volatile("cp.async.cg.shared.global [%0], [%1], 16;" :: "r"(dst), "l"(src + tid * 8));
}
#define CP_COMMIT() asm volatile("cp.async.commit_group;")
#define CP_WAIT(n)  asm volatile("cp.async.wait_group %0;" :: "n"(n))

// 32x32 score tile (K=64 fp16): B via 2x ldmatrix.x4 from staged slot.
__device__ __forceinline__ void mma_tile_h(const unsigned (&a)[4][4], unsigned addr, float o[4]){
    unsigned r[8];
    ldsm_x4(r,     addr);
    ldsm_x4(r + 4, addr + 64);
    o[0] = o[1] = o[2] = o[3] = 0.f;
    hmma16(o, a[0][0], a[0][1], a[0][2], a[0][3], r[0], r[1]);
    hmma16(o, a[1][0], a[1][1], a[1][2], a[1][3], r[2], r[3]);
    hmma16(o, a[2][0], a[2][1], a[2][2], a[2][3], r[4], r[5]);
    hmma16(o, a[3][0], a[3][1], a[3][2], a[3][3], r[6], r[7]);
}

__device__ __forceinline__ void ld_mask2(const char* __restrict__ mbase, size_t off, int mmode,
                                         int& m0, int& m1){
    if (mmode == 0){
        const int2 t = __ldcs(reinterpret_cast<const int2*>(mbase + 4 * off));
        m0 = t.x; m1 = t.y;
    } else if (mmode == 1){
        const unsigned char* p = reinterpret_cast<const unsigned char*>(mbase) + off;
        m0 = p[0]; m1 = p[1];
    } else {
        const float2 t = __ldcs(reinterpret_cast<const float2*>(mbase + 4 * off));
        m0 = (t.x != 0.f); m1 = (t.y != 0.f);
    }
}

extern __shared__ float smem[];

__global__ void __launch_bounds__(256, 3)
sdpa_kernel(const float* __restrict__ q, const char* __restrict__ mask,
            float* __restrict__ out, float* __restrict__ attn)
{
    unsigned* ShU = reinterpret_cast<unsigned*>(smem);          // S as half2 words
    float*    pan = smem + PAN_OFF;
    const unsigned sbase = (unsigned)__cvta_generic_to_shared(smem);
    const unsigned stg_b = sbase + STG_OFF * 4;
    #define KSLOT(s) (stg_b + (unsigned)(s) * (SLOT_U32 * 4))          // slots 0..2
    #define PSLOT(s) (stg_b + (unsigned)(3 + (s)) * (SLOT_U32 * 4))    // slots 3..5
    #define VSLOT(s) (stg_b + (unsigned)(s) * (SLOT_U32 * 4))          // 6-slot V ring

    const int tid  = threadIdx.x;
    const int w    = tid >> 5, lane = tid & 31;
    const int mw   = w & 1,    nw   = w >> 1;
    const int gr   = lane >> 2, c4  = lane & 3;
    const int b    = blockIdx.x >> 4;
    const int q0   = (blockIdx.x & 15) * 32;
    const int mmode = g_mask_mode;

    const __half* kh = g_kh + (size_t)b * L_ * DK_;
    const __half* vh = g_vh + (size_t)b * L_ * DK_;
    const __half* ph = g_ph + ((size_t)b * (2 * L_) + q0) * DK_;

    // ---- prologue prefetch: {k0,p0,p1}, {k1,p2} ----
    stage_cp(KSLOT(0), kh,            tid);
    stage_cp(PSLOT(0), ph,            tid);
    stage_cp(PSLOT(1), ph + 32 * DK_, tid);
    CP_COMMIT();
    stage_cp(KSLOT(1), kh + 32 * DK_, tid);
    stage_cp(PSLOT(2), ph + 64 * DK_, tid);
    CP_COMMIT();

    // ---- lane offsets for ldmatrix (bytes) ----
    const int li  = lane & 7, lg = lane >> 3;
    const unsigned qk_off  = (unsigned)((nw*8 + li) * (STH*4) + lg * 16);
    const unsigned pvA_off = (unsigned)((mw*16 + (lg&1)*8 + li) * (SSH*4) + (lg>>1) * 16);
    const unsigned pvB_off = (unsigned)(((lg&1)*8 + li) * (STH*4) + (nw*8 + (lg>>1)*4) * 4);

    // ---- Q A-fragments (fp16), persist entire kernel ----
    unsigned aqh[4][4];
    {
        const float* qb = q + ((size_t)b * L_ + q0 + mw * 16) * DK_;
        #pragma unroll
        for (int ks = 0; ks < 4; ++ks){
            const int dk0 = ks * 16 + 2 * c4;
            float2 t00 = *reinterpret_cast<const float2*>(qb + gr       * DK_ + dk0);
            float2 t10 = *reinterpret_cast<const float2*>(qb + (gr + 8) * DK_ + dk0);
            float2 t01 = *reinterpret_cast<const float2*>(qb + gr       * DK_ + dk0 + 8);
            float2 t11 = *reinterpret_cast<const float2*>(qb + (gr + 8) * DK_ + dk0 + 8);
            aqh[ks][0] = h2pack(t00.y, t00.x);
            aqh[ks][1] = h2pack(t10.y, t10.x);
            aqh[ks][2] = h2pack(t01.y, t01.x);
            aqh[ks][3] = h2pack(t11.y, t11.x);
        }
    }

    const int r0  = mw * 16 + gr;
    const int cbl = nw * 8 + 2 * c4;
    const size_t mrow0 = ((size_t)b * L_ + q0 + r0) * L_;
    const size_t mrow1 = mrow0 + (size_t)8 * L_;

    // ---- mask software pipeline: preload stage-0 values (overlaps prologue) ----
    int m00, m01, m10, m11;
    ld_mask2(mask, mrow0 + cbl, mmode, m00, m01);
    ld_mask2(mask, mrow1 + cbl, mmode, m10, m11);

    CP_WAIT(1);          // {k0,p0,p1} landed
    __syncthreads();

    // ---- bias panel 0 -> slot 0 ----
    {
        float c[4]; mma_tile_h(aqh, PSLOT(0) + qk_off, c);
        float* pd = pan;
        *reinterpret_cast<float2*>(pd + r0*PS + cbl)     = make_float2(c[0], c[1]);
        *reinterpret_cast<float2*>(pd + (r0+8)*PS + cbl) = make_float2(c[2], c[3]);
    }
    __syncthreads();     // P-slot 0 reads complete before st=0 overwrites it (mod-3 ring)

    // ---- QK loop: cp.async 2-stage prefetch, 1 sync/stage, 3 rotating panels,
    //      mask loads pipelined one stage ahead ----
    float psum0 = 0.f, psum1 = 0.f;

    #pragma unroll
    for (int st = 0; st < 16; ++st){
        const int slotA = st % 3;
        const int slotB = (st + 1) % 3;
        if (st < 14){
            stage_cp(KSLOT((st + 2) % 3), kh + (size_t)(st + 2) * 32 * DK_, tid);
            stage_cp(PSLOT(st % 3),       ph + (size_t)(st + 3) * 32 * DK_, tid);
        }
        CP_COMMIT();

        // issue next stage's mask loads early (consumed after next barrier)
        int n00, n01, n10, n11;
        if (st < 15){
            ld_mask2(mask, mrow0 + (st + 1) * 32 + cbl, mmode, n00, n01);
            ld_mask2(mask, mrow1 + (st + 1) * 32 + cbl, mmode, n10, n11);
        }

        // bias panel st+1 from p-ring slot (st+1)%3 -> pan slot slotB
        {
            float c[4];
            mma_tile_h(aqh, PSLOT((st + 1) % 3) + qk_off, c);
            float* pd = pan + slotB * (32 * PS);
            *reinterpret_cast<float2*>(pd + r0*PS + cbl)     = make_float2(c[0], c[1]);
            *reinterpret_cast<float2*>(pd + (r0+8)*PS + cbl) = make_float2(c[2], c[3]);
        }
        // QK stage st
        float s[4];
        mma_tile_h(aqh, KSLOT(st % 3) + qk_off, s);

        CP_WAIT(1);       // chunk set for stage st+1 landed
        __syncthreads();  // panel slotB visible; staging ring coherent

        const float* pA = pan + slotA * (32 * PS);
        const float* pB = pan + slotB * (32 * PS);
        {
            int i0 = r0, i1 = r0 + 8;
            int idx;
            idx = i0 + cbl;     float c0 = (idx < 32 ? pA : pB)[i0*PS + (idx & 31)];
            idx = i0 + cbl + 1; float c1 = (idx < 32 ? pA : pB)[i0*PS + (idx & 31)];
            idx = i1 + cbl;     float c2 = (idx < 32 ? pA : pB)[i1*PS + (idx & 31)];
            idx = i1 + cbl + 1; float c3 = (idx < 32 ? pA : pB)[i1*PS + (idx & 31)];
            s[0] = m00 ? 0.f : fexp4((s[0] + c0) * 0.125f);
            s[1] = m01 ? 0.f : fexp4((s[1] + c1) * 0.125f);
            s[2] = m10 ? 0.f : fexp4((s[2] + c2) * 0.125f);
            s[3] = m11 ? 0.f : fexp4((s[3] + c3) * 0.125f);
        }
        psum0 += s[0] + s[1];
        psum1 += s[2] + s[3];
        const int scol = st * 16 + nw * 4 + c4;
        ShU[r0      * SSH + scol] = h2pack(s[1], s[0]);
        ShU[(r0+8)  * SSH + scol] = h2pack(s[3], s[2]);

        if (st < 15){ m00 = n00; m01 = n01; m10 = n10; m11 = n11; }
    }
    __syncthreads();   // S(exp) writes + last panel reads complete

    // ---- V prefetch into 6-slot ring (hidden behind sum-reduce) ----
    stage_cp(VSLOT(0), vh,            tid);
    stage_cp(VSLOT(1), vh + 32 * DK_, tid);
    CP_COMMIT();
    stage_cp(VSLOT(2), vh + 64 * DK_, tid);
    stage_cp(VSLOT(3), vh + 96 * DK_, tid);
    CP_COMMIT();

    // ---- publish per-thread row sums ----
    float* sumbuf  = pan;          // 32*16 floats
    float* rinvbuf = pan + 1024;   // 32 floats
    sumbuf[r0 * 16 + nw * 4 + c4]       = psum0;
    sumbuf[(r0 + 8) * 16 + nw * 4 + c4] = psum1;
    __syncthreads();

    // ---- sum-reduce only: stash rinv (attn writes folded into PV loop) ----
    {
        const int row = tid >> 3, g = tid & 7;
        float sum = sumbuf[row * 16 + g] + sumbuf[row * 16 + g + 8];
        #pragma unroll
        for (int o = 4; o; o >>= 1) sum += __shfl_xor_sync(0xffffffffu, sum, o, 8);
        if (g == 0) rinvbuf[row] = 1.0f / sum;
    }
    CP_WAIT(1);        // v chunks 0,1 landed (2,3 may still be in flight)
    __syncthreads();   // rinvbuf + v0/v1 staging visible

    // ---- O = (P' @ V)_fp16 * rinv[row]; attn writes interleaved per super-stage ----
    {
        float o[2][4];
        #pragma unroll
        for (int tt = 0; tt < 2; ++tt)
            #pragma unroll
            for (int i = 0; i < 4; ++i) o[tt][i] = 0.f;

        const int row8 = tid >> 3, g8 = tid & 7;
        const unsigned* SrA = ShU + row8 * SSH;
        const float rinvA = rinvbuf[row8];
        float* ar = attn ? (attn + ((size_t)b * L_ + q0 + row8) * L_) : (float*)0;

        const unsigned aSa = sbase + pvA_off;
        #pragma unroll
        for (int s = 0; s < 8; ++s){
            if (s < 6){
                stage_cp(VSLOT((2*s + 4) % 6), vh + (size_t)(2*s + 4) * 32 * DK_, tid);
                stage_cp(VSLOT((2*s + 5) % 6), vh + (size_t)(2*s + 5) * 32 * DK_, tid);
            }
            CP_COMMIT();
            #pragma unroll
            for (int h = 0; h < 2; ++h){
                const int c = 2*s + h;
                unsigned aS[8];
                ldsm_x4(aS,     aSa + c * 64);
                ldsm_x4(aS + 4, aSa + c * 64 + 32);
                const unsigned vba = VSLOT(c % 6) + pvB_off;
                unsigned bV[8];
                ldsm_x4t(bV,     vba);
                ldsm_x4t(bV + 4, vba + 16 * STH * 4);
                hmma16(o[0], aS[0], aS[1], aS[2], aS[3], bV[0], bV[1]);
                hmma16(o[1], aS[0], aS[1], aS[2], aS[3], bV[2], bV[3]);
                hmma16(o[0], aS[4], aS[5], aS[6], aS[7], bV[4], bV[5]);
                hmma16(o[1], aS[4], aS[5], aS[6], aS[7], bV[6], bV[7]);
            }
            // attn chunks jj = 2s, 2s+1 (overlap STG with cp.async landing)
            if (ar){
                #pragma unroll
                for (int h = 0; h < 2; ++h){
                    const int jj = 2*s + h;
                    const int cw = jj * 16 + g8 * 2;
                    uint2 u = *reinterpret_cast<const uint2*>(SrA + cw);
                    float2 f01 = __half22float2(*reinterpret_cast<__half2*>(&u.x));
                    float2 f23 = __half22float2(*reinterpret_cast<__half2*>(&u.y));
                    float4 sv;
                    sv.x = f01.x * rinvA; sv.y = f01.y * rinvA;
                    sv.z = f23.x * rinvA; sv.w = f23.y * rinvA;
                    __stcs(reinterpret_cast<float4*>(ar + jj * 32 + g8 * 4), sv);
                }
            }
            CP_WAIT(1);
            __syncthreads();
        }
        const float rv0 = rinvbuf[r0];
        const float rv1 = rinvbuf[r0 + 8];
        #pragma unroll
        for (int tt = 0; tt < 2; ++tt){
            const int d0 = nw * 16 + tt * 8 + 2 * c4;
            size_t base0 = ((size_t)b * L_ + q0 + mw*16 + gr) * DK_ + d0;
            __stcs(reinterpret_cast<float2*>(out + base0),
                   make_float2(o[tt][0] * rv0, o[tt][1] * rv0));
            __stcs(reinterpret_cast<float2*>(out + base0 + (size_t)8 * DK_),
                   make_float2(o[tt][2] * rv1, o[tt][3] * rv1));
        }
    }
    #undef KSLOT
    #undef PSLOT
    #undef VSLOT
}

extern "C" void kernel_launch(void* const* d_in, const int* in_sizes, int n_in,
                              void* d_out, int out_size)
{
    const float* q   = (const float*)d_in[0];
    const float* k   = (const float*)d_in[1];
    const float* v   = (const float*)d_in[2];
    const float* pos = (const float*)d_in[3];
    const char*  mask = (const char*)d_in[4];
    float* out = (float*)d_out;

    const long long out_n = (long long)B_ * L_ * DK_;
    const long long att_n = (long long)B_ * L_ * L_;
    float* attn = ((long long)out_size >= out_n + att_n) ? (out + out_n) : nullptr;

    cvt_kernel<<<2048, 256>>>(k, v, pos, (const unsigned*)mask);

    const int smem_bytes = SMEM_U32 * 4;   // 74,752 B -> 3 CTAs/SM
    cudaFuncSetAttribute(sdpa_kernel, cudaFuncAttributeMaxDynamicSharedMemorySize, smem_bytes);
    sdpa_kernel<<<B_ * (L_ / 32), 256, smem_bytes>>>(q, mask, out, attn);
}